// round 10
// baseline (speedup 1.0000x reference)
#include <cuda_runtime.h>
#include <cstdint>

#define NB      128
#define CG      4              // block-columns per CTA
#define GROUPS  (NB / CG)      // 32
#define GCOLS   (CG * 32)      // 128
#define NTHR    256
#define MAXL    320
#define N_DIM   4096
#define BATCH   1024
#define NBLKS   4096

// SMEM layout (bytes, from dynamic base)
#define XS_STRIDE  36          // floats per x row (frag loads conflict-free)
#define XS_SLOT    (128 * XS_STRIDE * 4)   // 18432
#define BR_PITCH   40          // floats per raw-B row
#define BR_SLOT    (32 * BR_PITCH * 4)     // 5120
// Paired tf32 B: pr = kt*4+kq (16 rows), float2 slot [pr][n] = {B[k][n], B[k+4][n]}.
// PITCH >= 32 float2 (capacity) and PITCH mod 16 == 4 (conflict-free LDS.64) -> 36.
#define BP_PITCH   36
#define BP_SLOT    (16 * BP_PITCH * 8)     // 4608
#define XS_OFF     0u
#define BR_OFF     (4u * XS_SLOT)                    // 73728
#define BP_OFF     (BR_OFF + 4u * BR_SLOT)           // 94208
#define LIST_OFF   (BP_OFF + 2u * BP_SLOT)           // 103424
#define BIAS_OFF   (LIST_OFF + 4u * MAXL)            // 104704
#define SMEM_DYN   (BIAS_OFF + 4u * GCOLS)           // 105216

// ---------------- helpers ----------------

__device__ __forceinline__ uint32_t smem_u32(const void* p) {
    uint32_t a;
    asm("{ .reg .u64 t; cvta.to.shared.u64 t, %1; cvt.u32.u64 %0, t; }" : "=r"(a) : "l"(p));
    return a;
}
__device__ __forceinline__ void cpa16(uint32_t dst, const void* src) {
    asm volatile("cp.async.ca.shared.global [%0], [%1], 16;" :: "r"(dst), "l"(src));
}
#define CP_COMMIT() asm volatile("cp.async.commit_group;" ::: "memory")
#define CP_WAIT4()  asm volatile("cp.async.wait_group 4;" ::: "memory")

__device__ __forceinline__ float lds32(uint32_t a) {
    float v;
    asm volatile("ld.shared.f32 %0, [%1];" : "=f"(v) : "r"(a));
    return v;
}
__device__ __forceinline__ void lds64(uint32_t a, uint32_t& r0, uint32_t& r1) {
    asm volatile("ld.shared.v2.b32 {%0,%1}, [%2];" : "=r"(r0), "=r"(r1) : "r"(a));
}
__device__ __forceinline__ float4 lds128(uint32_t a) {
    float4 v;
    asm volatile("ld.shared.v4.f32 {%0,%1,%2,%3}, [%4];"
                 : "=f"(v.x), "=f"(v.y), "=f"(v.z), "=f"(v.w) : "r"(a));
    return v;
}
__device__ __forceinline__ void sts32(uint32_t a, uint32_t v) {
    asm volatile("st.shared.b32 [%0], %1;" :: "r"(a), "r"(v));
}
// cvt.rna.tf32.f32 requires a .b32 destination register -> "=r"
__device__ __forceinline__ uint32_t tf32b(float a) {
    uint32_t r;
    asm("cvt.rna.tf32.f32 %0, %1;" : "=r"(r) : "f"(a));
    return r;
}

#define MMA_TF32(C, A0, A1, A2, A3, B0, B1)                                       \
    asm volatile("mma.sync.aligned.m16n8k8.row.col.f32.tf32.tf32.f32 "            \
                 "{%0,%1,%2,%3},{%4,%5,%6,%7},{%8,%9},{%0,%1,%2,%3};"             \
                 : "+f"((C)[0]), "+f"((C)[1]), "+f"((C)[2]), "+f"((C)[3])         \
                 : "r"(A0), "r"(A1), "r"(A2), "r"(A3), "r"(B0), "r"(B1))

// ---------------- work lists ----------------
// entry: n[0:12) | cib[12:19) | lco[19:21); list preserves sorted (ci,co) order.

__device__ int g_cnt[GROUPS];
__device__ int g_list[GROUPS * MAXL];

__global__ void build_lists_kernel(const int* __restrict__ ci, const int* __restrict__ co) {
    __shared__ int pref[NTHR];
    const int g = blockIdx.x;
    const int t = threadIdx.x;
    const int base = t * (NBLKS / NTHR);   // 16 entries per thread
    int cnt = 0;
#pragma unroll
    for (int j = 0; j < NBLKS / NTHR; j++)
        if ((co[base + j] >> 2) == g) cnt++;
    pref[t] = cnt;
    __syncthreads();
    for (int off = 1; off < NTHR; off <<= 1) {
        int v = (t >= off) ? pref[t - off] : 0;
        __syncthreads();
        pref[t] += v;
        __syncthreads();
    }
    int pos = pref[t] - cnt;
#pragma unroll
    for (int j = 0; j < NBLKS / NTHR; j++) {
        int n = base + j;
        int c = co[n];
        if ((c >> 2) == g) {
            g_list[g * MAXL + pos] = n | (ci[n] << 12) | ((c & 3) << 19);
            pos++;
        }
    }
    if (t == NTHR - 1) g_cnt[g] = pref[NTHR - 1];
}

// ---------------- per-block compute ----------------
// PTX m16n8k8.row.col A layout (row = lane>>2, col = lane&3):
//   a0=(row,col) a1=(row+8,col) a2=(row,col+4) a3=(row+8,col+4)
// B fragment: b0=(k=lane&3, n=lane>>2), b1=(k+4, n) -> one LDS.64 from paired buf.

template <int LCO>
__device__ __forceinline__ void compute_block(float (&acc)[16][4],
                                              const uint32_t (&afr)[4][4],
                                              uint32_t bpb, int kq, int nq) {
#pragma unroll
    for (int kt = 0; kt < 4; kt++) {
        uint32_t rowa = bpb + 8u * ((uint32_t)(kt * 4 + kq) * BP_PITCH + nq);
#pragma unroll
        for (int nt = 0; nt < 4; nt++) {
            uint32_t b0, b1;
            lds64(rowa + 8u * (uint32_t)(nt * 8), b0, b1);
            MMA_TF32(acc[4 * LCO + nt], afr[kt][0], afr[kt][1], afr[kt][2], afr[kt][3], b0, b1);
        }
    }
}

__device__ __forceinline__ void load_afrags(uint32_t (&afr)[4][4], uint32_t xs_warp,
                                            int kq, int nq) {
#pragma unroll
    for (int kt = 0; kt < 4; kt++) {
        uint32_t r0 = xs_warp + 4u * ((uint32_t)nq * XS_STRIDE + kt * 8 + kq);
        afr[kt][0] = tf32b(lds32(r0));                              // (row,   col)
        afr[kt][1] = tf32b(lds32(r0 + 8u * XS_STRIDE * 4u));        // (row+8, col)
        afr[kt][2] = tf32b(lds32(r0 + 16u));                        // (row,   col+4)
        afr[kt][3] = tf32b(lds32(r0 + 8u * XS_STRIDE * 4u + 16u));  // (row+8, col+4)
    }
}

// ---------------- main kernel ----------------

__global__ void __launch_bounds__(NTHR, 2)
bs_mma_kernel(const float* __restrict__ x, const float* __restrict__ kern,
              const float* __restrict__ bias, float* __restrict__ out) {
    extern __shared__ char smem_raw[];
    const uint32_t base = smem_u32(smem_raw);
    int* list_s = (int*)(smem_raw + LIST_OFF);
    float* bias_s = (float*)(smem_raw + BIAS_OFF);

    const int g   = blockIdx.x;
    const int by  = blockIdx.y;
    const int tid = threadIdx.x;
    const int w   = tid >> 5;
    const int lane = tid & 31;
    const int kq  = lane & 3;
    const int nq  = lane >> 2;

    const int cnt = g_cnt[g];
    for (int j = tid; j < cnt; j += NTHR) list_s[j] = g_list[g * MAXL + j];
    if (tid < GCOLS) bias_s[tid] = bias[g * GCOLS + tid];
    __syncthreads();

    float acc[16][4];
#pragma unroll
    for (int i = 0; i < 16; i++)
#pragma unroll
        for (int j = 0; j < 4; j++) acc[i][j] = 0.f;

    const float* xrow0 = x + (size_t)(by * 128) * N_DIM;

    auto stage_x = [&](int cib, int slot) {
        const float* src = xrow0 + cib * 32;
        uint32_t dst = base + XS_OFF + (uint32_t)slot * XS_SLOT;
#pragma unroll
        for (int j = 0; j < 4; j++) {
            int id = tid + j * NTHR;        // 0..1023 float4 slots
            int row = id >> 3, c4 = id & 7;
            cpa16(dst + (uint32_t)row * (XS_STRIDE * 4) + c4 * 16u,
                  src + (size_t)row * N_DIM + c4 * 4);
        }
    };
    // raw B staging: thread owns row k = tid>>3, cols n0..n0+3
    const int bk  = tid >> 3;
    const int bn0 = 4 * (tid & 7);
    auto stage_braw = [&](int n, int slot) {
        cpa16(base + BR_OFF + (uint32_t)slot * BR_SLOT + 4u * ((uint32_t)bk * BR_PITCH + bn0),
              kern + (size_t)n * 1024 + bk * 32 + bn0);
    };
    // convert raw B (slot j&3) -> tf32 paired buffer (slot j&1).
    // Reads only this thread's own staged bytes -> own wait_group covers it.
    const int bpr = ((bk >> 3) << 2) | (bk & 3);
    const int be  = (bk >> 2) & 1;
    auto convert_b = [&](int j) {
        float4 v = lds128(base + BR_OFF + (uint32_t)(j & 3) * BR_SLOT +
                          4u * ((uint32_t)bk * BR_PITCH + bn0));
        uint32_t a0 = base + BP_OFF + (uint32_t)(j & 1) * BP_SLOT +
                      8u * ((uint32_t)bpr * BP_PITCH + bn0) + (uint32_t)be * 4u;
        sts32(a0,       tf32b(v.x));
        sts32(a0 + 8u,  tf32b(v.y));
        sts32(a0 + 16u, tf32b(v.z));
        sts32(a0 + 24u, tf32b(v.w));
    };

    if (cnt > 0) {
        int staged_cib = -1, staged_slot = 3;
        int s0 = 0, s1 = 0, s2 = 0;

        auto px = [&](int j) -> int {     // stage x run for entry j if new
            int e = list_s[j];
            int cib = (e >> 12) & 127;
            if (cib != staged_cib) {
                staged_slot = (staged_slot + 1) & 3;
                stage_x(cib, staged_slot);
                staged_cib = cib;
            }
            return staged_slot;
        };

        // Prologue: 5 groups, strict order B0, X0, B1, X1, B2
        stage_braw(list_s[0] & 0xFFF, 0);               CP_COMMIT();
        s0 = px(0);                                      CP_COMMIT();
        if (cnt > 1) stage_braw(list_s[1] & 0xFFF, 1);  CP_COMMIT();
        s1 = (cnt > 1) ? px(1) : s0;                     CP_COMMIT();
        if (cnt > 2) stage_braw(list_s[2] & 0xFFF, 2);  CP_COMMIT();
        CP_WAIT4();            // B0 done (own bytes)
        convert_b(0);          // BP slot 0 ready for body 0 (after sync below)

        uint32_t afr[4][4];
        int frag_cib = -1;

        for (int i = 0; i < cnt; i++) {
            // per-iter commits: [B(i+3)], [X(run i+2)] -> wait4 guarantees
            // B(i+1) and X(run i) complete (each committed 2 iterations ago)
            if (i + 3 < cnt) stage_braw(list_s[i + 3] & 0xFFF, (i + 3) & 3);
            CP_COMMIT();
            s2 = (i + 2 < cnt) ? px(i + 2) : s1;
            CP_COMMIT();
            CP_WAIT4();
            __syncthreads();       // all threads' iter-i data + prev converts visible

            if (i + 1 < cnt) convert_b(i + 1);

            int vi  = list_s[i];
            int lco = (vi >> 19) & 3;
            int cib_i = (vi >> 12) & 127;

            if (cib_i != frag_cib) {
                load_afrags(afr, base + XS_OFF + (uint32_t)s0 * XS_SLOT +
                                 (uint32_t)(16 * w) * (XS_STRIDE * 4), kq, nq);
                frag_cib = cib_i;
            }

            uint32_t bpb = base + BP_OFF + (uint32_t)(i & 1) * BP_SLOT;
            switch (lco) {
                case 0: compute_block<0>(acc, afr, bpb, kq, nq); break;
                case 1: compute_block<1>(acc, afr, bpb, kq, nq); break;
                case 2: compute_block<2>(acc, afr, bpb, kq, nq); break;
                default: compute_block<3>(acc, afr, bpb, kq, nq); break;
            }

            s0 = s1; s1 = s2;
        }
    }

    // ---- epilogue: bias + relu ----
    {
        int r = 16 * w + nq;
        size_t rb0 = (size_t)(by * 128 + r) * N_DIM + g * GCOLS;
        size_t rb1 = rb0 + 8 * (size_t)N_DIM;
#pragma unroll
        for (int nt = 0; nt < 16; nt++) {
            int c = nt * 8 + 2 * kq;
            float b0 = bias_s[c], b1 = bias_s[c + 1];
            float2 v0, v1;
            v0.x = fmaxf(acc[nt][0] + b0, 0.f);
            v0.y = fmaxf(acc[nt][1] + b1, 0.f);
            v1.x = fmaxf(acc[nt][2] + b0, 0.f);
            v1.y = fmaxf(acc[nt][3] + b1, 0.f);
            *(float2*)(out + rb0 + c) = v0;
            *(float2*)(out + rb1 + c) = v1;
        }
    }
}

extern "C" void kernel_launch(void* const* d_in, const int* in_sizes, int n_in,
                              void* d_out, int out_size) {
    const float* x    = (const float*)d_in[0];
    const float* kern = (const float*)d_in[1];
    const float* bias = (const float*)d_in[2];
    const int*   ci   = (const int*)d_in[3];
    const int*   co   = (const int*)d_in[4];
    float* out = (float*)d_out;

    cudaFuncSetAttribute(bs_mma_kernel, cudaFuncAttributeMaxDynamicSharedMemorySize, SMEM_DYN);

    build_lists_kernel<<<GROUPS, NTHR>>>(ci, co);
    dim3 grid(GROUPS, BATCH / 128);
    bs_mma_kernel<<<grid, NTHR, SMEM_DYN>>>(x, kern, bias, out);
}

// round 11
// speedup vs baseline: 1.1628x; 1.1628x over previous
#include <cuda_runtime.h>
#include <cstdint>

#define NB      128
#define CG      4              // block-columns per CTA
#define GROUPS  (NB / CG)      // 32
#define GCOLS   (CG * 32)      // 128
#define NTHR    256
#define MAXL    320
#define N_DIM   4096
#define BATCH   1024
#define NBLKS   4096

// SMEM layout (bytes, from dynamic base)
#define XS_STRIDE  36          // 36 mod 32 = 4 -> 4nq+kq bijective: conflict-free
#define XS_SLOT    (128 * XS_STRIDE * 4)   // 18432
#define BR_PITCH   40          // 40 mod 32 = 8 -> 8kq+nq bijective: conflict-free
#define BR_SLOT    (32 * BR_PITCH * 4)     // 5120
#define XS_OFF     0u
#define BR_OFF     (4u * XS_SLOT)                    // 73728
#define LIST_OFF   (BR_OFF + 4u * BR_SLOT)           // 94208
#define BIAS_OFF   (LIST_OFF + 4u * MAXL)            // 95488
#define SMEM_DYN   (BIAS_OFF + 4u * GCOLS)           // 96000 -> 2 CTAs/SM fits

// ---------------- helpers ----------------

__device__ __forceinline__ uint32_t smem_u32(const void* p) {
    uint32_t a;
    asm("{ .reg .u64 t; cvta.to.shared.u64 t, %1; cvt.u32.u64 %0, t; }" : "=r"(a) : "l"(p));
    return a;
}
__device__ __forceinline__ void cpa16(uint32_t dst, const void* src) {
    asm volatile("cp.async.ca.shared.global [%0], [%1], 16;" :: "r"(dst), "l"(src));
}
#define CP_COMMIT() asm volatile("cp.async.commit_group;" ::: "memory")
#define CP_WAIT0()  asm volatile("cp.async.wait_group 0;" ::: "memory")

__device__ __forceinline__ float lds32(uint32_t a) {
    float v;
    asm volatile("ld.shared.f32 %0, [%1];" : "=f"(v) : "r"(a));
    return v;
}
// cvt.rna.tf32.f32 requires a .b32 destination register -> "=r"
__device__ __forceinline__ uint32_t tf32b(float a) {
    uint32_t r;
    asm("cvt.rna.tf32.f32 %0, %1;" : "=r"(r) : "f"(a));
    return r;
}

#define MMA_TF32(C, A0, A1, A2, A3, B0, B1)                                       \
    asm volatile("mma.sync.aligned.m16n8k8.row.col.f32.tf32.tf32.f32 "            \
                 "{%0,%1,%2,%3},{%4,%5,%6,%7},{%8,%9},{%0,%1,%2,%3};"             \
                 : "+f"((C)[0]), "+f"((C)[1]), "+f"((C)[2]), "+f"((C)[3])         \
                 : "r"(A0), "r"(A1), "r"(A2), "r"(A3), "r"(B0), "r"(B1))

// ---------------- work lists ----------------
// entry: n[0:12) | cib[12:19) | lco[19:21); list preserves sorted (ci,co) order.

__device__ int g_cnt[GROUPS];
__device__ int g_list[GROUPS * MAXL];

__global__ void build_lists_kernel(const int* __restrict__ ci, const int* __restrict__ co) {
    __shared__ int pref[NTHR];
    const int g = blockIdx.x;
    const int t = threadIdx.x;
    const int base = t * (NBLKS / NTHR);   // 16 entries per thread
    int cnt = 0;
#pragma unroll
    for (int j = 0; j < NBLKS / NTHR; j++)
        if ((co[base + j] >> 2) == g) cnt++;
    pref[t] = cnt;
    __syncthreads();
    for (int off = 1; off < NTHR; off <<= 1) {
        int v = (t >= off) ? pref[t - off] : 0;
        __syncthreads();
        pref[t] += v;
        __syncthreads();
    }
    int pos = pref[t] - cnt;
#pragma unroll
    for (int j = 0; j < NBLKS / NTHR; j++) {
        int n = base + j;
        int c = co[n];
        if ((c >> 2) == g) {
            g_list[g * MAXL + pos] = n | (ci[n] << 12) | ((c & 3) << 19);
            pos++;
        }
    }
    if (t == NTHR - 1) g_cnt[g] = pref[NTHR - 1];
}

// ---------------- per-block compute ----------------
// PTX m16n8k8.row.col A layout (row = lane>>2, col = lane&3):
//   a0=(row,col) a1=(row+8,col) a2=(row,col+4) a3=(row+8,col+4)
// B fragment: b0=(k=lane&3, n=lane>>2), b1=(k+4, n); raw-B rows (pitch 40),
// tf32 cvt inline. 40 mod 32 = 8 -> per-LDS lane banks 8kq+nq: conflict-free.

template <int LCO>
__device__ __forceinline__ void compute_block(float (&acc)[16][4],
                                              const uint32_t (&afr)[4][4],
                                              uint32_t brb, int kq, int nq) {
#pragma unroll
    for (int kt = 0; kt < 4; kt++) {
        uint32_t rowa = brb + 4u * ((uint32_t)(kt * 8 + kq) * BR_PITCH + nq);
#pragma unroll
        for (int nt = 0; nt < 4; nt++) {
            uint32_t a  = rowa + 4u * (uint32_t)(nt * 8);
            uint32_t b0 = tf32b(lds32(a));
            uint32_t b1 = tf32b(lds32(a + 4u * 4 * BR_PITCH));
            MMA_TF32(acc[4 * LCO + nt], afr[kt][0], afr[kt][1], afr[kt][2], afr[kt][3], b0, b1);
        }
    }
}

__device__ __forceinline__ void load_afrags(uint32_t (&afr)[4][4], uint32_t xs_warp,
                                            int kq, int nq) {
#pragma unroll
    for (int kt = 0; kt < 4; kt++) {
        uint32_t r0 = xs_warp + 4u * ((uint32_t)nq * XS_STRIDE + kt * 8 + kq);
        afr[kt][0] = tf32b(lds32(r0));                              // (row,   col)
        afr[kt][1] = tf32b(lds32(r0 + 8u * XS_STRIDE * 4u));        // (row+8, col)
        afr[kt][2] = tf32b(lds32(r0 + 16u));                        // (row,   col+4)
        afr[kt][3] = tf32b(lds32(r0 + 8u * XS_STRIDE * 4u + 16u));  // (row+8, col+4)
    }
}

// ---------------- main kernel ----------------
// Super-iteration s handles blocks 2s, 2s+1:
//   wait_group 0  -> this thread's copies from super-iter s-1 complete
//   __syncthreads -> all threads passed their wait: all staged data visible
//   stage X/B for blocks 2s+2, 2s+3 (one commit group; overlaps with compute)
//   compute blocks 2s, 2s+1
// Races (stage after sync): B writes slots {2s+2,2s+3}&3 vs reads {2s,2s+1}&3
// disjoint; X live-run window = blocks 2s..2s+3 <= 4 runs -> 4-slot ring safe.

__global__ void __launch_bounds__(NTHR, 2)
bs_mma_kernel(const float* __restrict__ x, const float* __restrict__ kern,
              const float* __restrict__ bias, float* __restrict__ out) {
    extern __shared__ char smem_raw[];
    const uint32_t base = smem_u32(smem_raw);
    int* list_s = (int*)(smem_raw + LIST_OFF);
    float* bias_s = (float*)(smem_raw + BIAS_OFF);

    const int g   = blockIdx.x;
    const int by  = blockIdx.y;
    const int tid = threadIdx.x;
    const int w   = tid >> 5;
    const int lane = tid & 31;
    const int kq  = lane & 3;
    const int nq  = lane >> 2;

    const int cnt = g_cnt[g];
    for (int j = tid; j < cnt; j += NTHR) list_s[j] = g_list[g * MAXL + j];
    if (tid < GCOLS) bias_s[tid] = bias[g * GCOLS + tid];
    __syncthreads();

    float acc[16][4];
#pragma unroll
    for (int i = 0; i < 16; i++)
#pragma unroll
        for (int j = 0; j < 4; j++) acc[i][j] = 0.f;

    const float* xrow0 = x + (size_t)(by * 128) * N_DIM;

    auto stage_x = [&](int cib, int slot) {
        const float* src = xrow0 + cib * 32;
        uint32_t dst = base + XS_OFF + (uint32_t)slot * XS_SLOT;
#pragma unroll
        for (int j = 0; j < 4; j++) {
            int id = tid + j * NTHR;        // 0..1023 float4 slots
            int row = id >> 3, c4 = id & 7;
            cpa16(dst + (uint32_t)row * (XS_STRIDE * 4) + c4 * 16u,
                  src + (size_t)row * N_DIM + c4 * 4);
        }
    };
    // raw B staging: thread owns row k = tid>>3, cols n0..n0+3
    const int bk  = tid >> 3;
    const int bn0 = 4 * (tid & 7);
    auto stage_braw = [&](int n, int slot) {
        cpa16(base + BR_OFF + (uint32_t)slot * BR_SLOT + 4u * ((uint32_t)bk * BR_PITCH + bn0),
              kern + (size_t)n * 1024 + bk * 32 + bn0);
    };

    if (cnt > 0) {
        int staged_cib = -1, staged_slot = 3;
        auto px = [&](int j) -> int {     // stage x run for entry j if new
            int e = list_s[j];
            int cib = (e >> 12) & 127;
            if (cib != staged_cib) {
                staged_slot = (staged_slot + 1) & 3;
                stage_x(cib, staged_slot);
                staged_cib = cib;
            }
            return staged_slot;
        };

        // prologue: stage blocks 0,1 (one group)
        int q0 = px(0);
        stage_braw(list_s[0] & 0xFFF, 0);
        int q1 = q0;
        if (cnt > 1) { q1 = px(1); stage_braw(list_s[1] & 0xFFF, 1); }
        CP_COMMIT();

        uint32_t afr[4][4];
        int frag_cib = -1;
        const int S = (cnt + 1) >> 1;

        for (int s = 0; s < S; s++) {
            const int i0 = 2 * s, i1 = 2 * s + 1;

            CP_WAIT0();            // own copies from previous super-iter done
            __syncthreads();       // everyone waited -> all staged data visible

            // stage blocks i0+2, i1+2 (overlaps with compute below)
            int q2 = q1, q3 = q1;
            if (i0 + 2 < cnt) { q2 = px(i0 + 2); stage_braw(list_s[i0 + 2] & 0xFFF, (i0 + 2) & 3); }
            if (i1 + 2 < cnt) { q3 = px(i1 + 2); stage_braw(list_s[i1 + 2] & 0xFFF, (i1 + 2) & 3); }
            CP_COMMIT();

            // ---- compute block i0 ----
            {
                int vi  = list_s[i0];
                int lco = (vi >> 19) & 3;
                int cib = (vi >> 12) & 127;
                if (cib != frag_cib) {
                    load_afrags(afr, base + XS_OFF + (uint32_t)q0 * XS_SLOT +
                                     (uint32_t)(16 * w) * (XS_STRIDE * 4), kq, nq);
                    frag_cib = cib;
                }
                uint32_t brb = base + BR_OFF + (uint32_t)(i0 & 3) * BR_SLOT;
                switch (lco) {
                    case 0: compute_block<0>(acc, afr, brb, kq, nq); break;
                    case 1: compute_block<1>(acc, afr, brb, kq, nq); break;
                    case 2: compute_block<2>(acc, afr, brb, kq, nq); break;
                    default: compute_block<3>(acc, afr, brb, kq, nq); break;
                }
            }
            // ---- compute block i1 ----
            if (i1 < cnt) {
                int vi  = list_s[i1];
                int lco = (vi >> 19) & 3;
                int cib = (vi >> 12) & 127;
                if (cib != frag_cib) {
                    load_afrags(afr, base + XS_OFF + (uint32_t)q1 * XS_SLOT +
                                     (uint32_t)(16 * w) * (XS_STRIDE * 4), kq, nq);
                    frag_cib = cib;
                }
                uint32_t brb = base + BR_OFF + (uint32_t)(i1 & 3) * BR_SLOT;
                switch (lco) {
                    case 0: compute_block<0>(acc, afr, brb, kq, nq); break;
                    case 1: compute_block<1>(acc, afr, brb, kq, nq); break;
                    case 2: compute_block<2>(acc, afr, brb, kq, nq); break;
                    default: compute_block<3>(acc, afr, brb, kq, nq); break;
                }
            }

            q0 = q2; q1 = q3;
        }
    }

    // ---- epilogue: bias + relu ----
    {
        int r = 16 * w + nq;
        size_t rb0 = (size_t)(by * 128 + r) * N_DIM + g * GCOLS;
        size_t rb1 = rb0 + 8 * (size_t)N_DIM;
#pragma unroll
        for (int nt = 0; nt < 16; nt++) {
            int c = nt * 8 + 2 * kq;
            float b0 = bias_s[c], b1 = bias_s[c + 1];
            float2 v0, v1;
            v0.x = fmaxf(acc[nt][0] + b0, 0.f);
            v0.y = fmaxf(acc[nt][1] + b1, 0.f);
            v1.x = fmaxf(acc[nt][2] + b0, 0.f);
            v1.y = fmaxf(acc[nt][3] + b1, 0.f);
            *(float2*)(out + rb0 + c) = v0;
            *(float2*)(out + rb1 + c) = v1;
        }
    }
}

extern "C" void kernel_launch(void* const* d_in, const int* in_sizes, int n_in,
                              void* d_out, int out_size) {
    const float* x    = (const float*)d_in[0];
    const float* kern = (const float*)d_in[1];
    const float* bias = (const float*)d_in[2];
    const int*   ci   = (const int*)d_in[3];
    const int*   co   = (const int*)d_in[4];
    float* out = (float*)d_out;

    cudaFuncSetAttribute(bs_mma_kernel, cudaFuncAttributeMaxDynamicSharedMemorySize, SMEM_DYN);

    build_lists_kernel<<<GROUPS, NTHR>>>(ci, co);
    dim3 grid(GROUPS, BATCH / 128);
    bs_mma_kernel<<<grid, NTHR, SMEM_DYN>>>(x, kern, bias, out);
}

// round 12
// speedup vs baseline: 1.3315x; 1.1451x over previous
#include <cuda_runtime.h>
#include <cstdint>

#define NB      128
#define CG      4              // block-columns per CTA
#define GROUPS  (NB / CG)      // 32
#define GCOLS   (CG * 32)      // 128
#define NTHR    256
#define MAXL    320
#define N_DIM   4096
#define BATCH   1024
#define NBLKS   4096

// SMEM layout (bytes, from dynamic base)
#define XS_STRIDE  36          // 36 mod 32 = 4 -> 4nq+kq bijective: conflict-free
#define XS_SLOT    (128 * XS_STRIDE * 4)   // 18432
// Paired tf32 B staged from pre-converted global: 16 pair-rows x 32 float2.
// pr = kt*4+kq, k = (pr>>2)*8 + (pr&3); slot [pr][n] = {B[k][n], B[k+4][n]}.
// SMEM pitch 36 float2: >=32 (capacity) and mod 16 == 4 (conflict-free LDS.64).
#define BP_PITCH   36
#define BP_SLOT    (16 * BP_PITCH * 8)     // 4608
#define XS_OFF     0u
#define BP_OFF     (4u * XS_SLOT)                    // 73728
#define LIST_OFF   (BP_OFF + 4u * BP_SLOT)           // 92160
#define BIAS_OFF   (LIST_OFF + 4u * MAXL)            // 93440
#define SMEM_DYN   (BIAS_OFF + 4u * GCOLS)           // 93952 -> 2 CTAs/SM fits

// Pre-converted paired-tf32 kernel blocks: [block][pr (16)][float4 chunk (16)]
// float4 = {B[k][o], B[k+4][o], B[k][o+1], B[k+4][o+1]} -> 2 float2 slots.
__device__ float4 g_bp[NBLKS * 256];   // 16 MB

// ---------------- helpers ----------------

__device__ __forceinline__ uint32_t smem_u32(const void* p) {
    uint32_t a;
    asm("{ .reg .u64 t; cvta.to.shared.u64 t, %1; cvt.u32.u64 %0, t; }" : "=r"(a) : "l"(p));
    return a;
}
__device__ __forceinline__ void cpa16(uint32_t dst, const void* src) {
    asm volatile("cp.async.ca.shared.global [%0], [%1], 16;" :: "r"(dst), "l"(src));
}
#define CP_COMMIT() asm volatile("cp.async.commit_group;" ::: "memory")
#define CP_WAIT0()  asm volatile("cp.async.wait_group 0;" ::: "memory")

__device__ __forceinline__ float lds32(uint32_t a) {
    float v;
    asm volatile("ld.shared.f32 %0, [%1];" : "=f"(v) : "r"(a));
    return v;
}
__device__ __forceinline__ void lds64(uint32_t a, uint32_t& r0, uint32_t& r1) {
    asm volatile("ld.shared.v2.b32 {%0,%1}, [%2];" : "=r"(r0), "=r"(r1) : "r"(a));
}
// cvt.rna.tf32.f32 requires a .b32 destination register -> "=r"
__device__ __forceinline__ uint32_t tf32b(float a) {
    uint32_t r;
    asm("cvt.rna.tf32.f32 %0, %1;" : "=r"(r) : "f"(a));
    return r;
}

#define MMA_TF32(C, A0, A1, A2, A3, B0, B1)                                       \
    asm volatile("mma.sync.aligned.m16n8k8.row.col.f32.tf32.tf32.f32 "            \
                 "{%0,%1,%2,%3},{%4,%5,%6,%7},{%8,%9},{%0,%1,%2,%3};"             \
                 : "+f"((C)[0]), "+f"((C)[1]), "+f"((C)[2]), "+f"((C)[3])         \
                 : "r"(A0), "r"(A1), "r"(A2), "r"(A3), "r"(B0), "r"(B1))

// ---------------- prep kernels ----------------

// Reformat kern -> g_bp (tf32, paired fragment layout). One float4 per thread.
__global__ void convert_b_kernel(const float* __restrict__ kern) {
    int idx = blockIdx.x * 256 + threadIdx.x;     // 0 .. NBLKS*256-1
    int n  = idx >> 8;
    int r  = idx & 255;
    int pr = r >> 4;            // pair-row 0..15
    int o  = (r & 15) * 2;      // output col 0..30 step 2
    int k  = ((pr >> 2) << 3) | (pr & 3);
    const float* kb = kern + (size_t)n * 1024;
    float4 v;
    v.x = __uint_as_float(tf32b(kb[k * 32 + o]));
    v.y = __uint_as_float(tf32b(kb[(k + 4) * 32 + o]));
    v.z = __uint_as_float(tf32b(kb[k * 32 + o + 1]));
    v.w = __uint_as_float(tf32b(kb[(k + 4) * 32 + o + 1]));
    g_bp[idx] = v;
}

// ---------------- work lists ----------------
// entry: n[0:12) | cib[12:19) | lco[19:21); list preserves sorted (ci,co) order.

__device__ int g_cnt[GROUPS];
__device__ int g_list[GROUPS * MAXL];

__global__ void build_lists_kernel(const int* __restrict__ ci, const int* __restrict__ co) {
    __shared__ int pref[NTHR];
    const int g = blockIdx.x;
    const int t = threadIdx.x;
    const int base = t * (NBLKS / NTHR);   // 16 entries per thread
    int cnt = 0;
#pragma unroll
    for (int j = 0; j < NBLKS / NTHR; j++)
        if ((co[base + j] >> 2) == g) cnt++;
    pref[t] = cnt;
    __syncthreads();
    for (int off = 1; off < NTHR; off <<= 1) {
        int v = (t >= off) ? pref[t - off] : 0;
        __syncthreads();
        pref[t] += v;
        __syncthreads();
    }
    int pos = pref[t] - cnt;
#pragma unroll
    for (int j = 0; j < NBLKS / NTHR; j++) {
        int n = base + j;
        int c = co[n];
        if ((c >> 2) == g) {
            g_list[g * MAXL + pos] = n | (ci[n] << 12) | ((c & 3) << 19);
            pos++;
        }
    }
    if (t == NTHR - 1) g_cnt[g] = pref[NTHR - 1];
}

// ---------------- per-block compute ----------------
// PTX m16n8k8.row.col A layout (row = lane>>2, col = lane&3):
//   a0=(row,col) a1=(row+8,col) a2=(row,col+4) a3=(row+8,col+4)
// B fragment: b0=(k=lane&3, n=lane>>2), b1=(k+4, n) -> one LDS.64 from paired buf.

template <int LCO>
__device__ __forceinline__ void compute_block(float (&acc)[16][4],
                                              const uint32_t (&afr)[4][4],
                                              uint32_t bpb, int kq, int nq) {
#pragma unroll
    for (int kt = 0; kt < 4; kt++) {
        uint32_t rowa = bpb + 8u * ((uint32_t)(kt * 4 + kq) * BP_PITCH + nq);
#pragma unroll
        for (int nt = 0; nt < 4; nt++) {
            uint32_t b0, b1;
            lds64(rowa + 8u * (uint32_t)(nt * 8), b0, b1);
            MMA_TF32(acc[4 * LCO + nt], afr[kt][0], afr[kt][1], afr[kt][2], afr[kt][3], b0, b1);
        }
    }
}

__device__ __forceinline__ void load_afrags(uint32_t (&afr)[4][4], uint32_t xs_warp,
                                            int kq, int nq) {
#pragma unroll
    for (int kt = 0; kt < 4; kt++) {
        uint32_t r0 = xs_warp + 4u * ((uint32_t)nq * XS_STRIDE + kt * 8 + kq);
        afr[kt][0] = tf32b(lds32(r0));                              // (row,   col)
        afr[kt][1] = tf32b(lds32(r0 + 8u * XS_STRIDE * 4u));        // (row+8, col)
        afr[kt][2] = tf32b(lds32(r0 + 16u));                        // (row,   col+4)
        afr[kt][3] = tf32b(lds32(r0 + 8u * XS_STRIDE * 4u + 16u));  // (row+8, col+4)
    }
}

// ---------------- main kernel ----------------
// Super-iteration s handles blocks 2s, 2s+1:
//   wait_group 0 -> sync -> stage blocks 2s+2, 2s+3 -> compute 2s, 2s+1.
// B ring 4: writes {2s+2,2s+3}&3 vs reads {2s,2s+1}&3 disjoint.
// X ring 4: live-run window = blocks 2s..2s+3 <= 4 runs.

__global__ void __launch_bounds__(NTHR, 2)
bs_mma_kernel(const float* __restrict__ x, const float* __restrict__ bias,
              float* __restrict__ out) {
    extern __shared__ char smem_raw[];
    const uint32_t base = smem_u32(smem_raw);
    int* list_s = (int*)(smem_raw + LIST_OFF);
    float* bias_s = (float*)(smem_raw + BIAS_OFF);

    const int g   = blockIdx.x;
    const int by  = blockIdx.y;
    const int tid = threadIdx.x;
    const int w   = tid >> 5;
    const int lane = tid & 31;
    const int kq  = lane & 3;
    const int nq  = lane >> 2;

    const int cnt = g_cnt[g];
    for (int j = tid; j < cnt; j += NTHR) list_s[j] = g_list[g * MAXL + j];
    if (tid < GCOLS) bias_s[tid] = bias[g * GCOLS + tid];
    __syncthreads();

    float acc[16][4];
#pragma unroll
    for (int i = 0; i < 16; i++)
#pragma unroll
        for (int j = 0; j < 4; j++) acc[i][j] = 0.f;

    const float* xrow0 = x + (size_t)(by * 128) * N_DIM;

    auto stage_x = [&](int cib, int slot) {
        const float* src = xrow0 + cib * 32;
        uint32_t dst = base + XS_OFF + (uint32_t)slot * XS_SLOT;
#pragma unroll
        for (int j = 0; j < 4; j++) {
            int id = tid + j * NTHR;        // 0..1023 float4 slots
            int row = id >> 3, c4 = id & 7;
            cpa16(dst + (uint32_t)row * (XS_STRIDE * 4) + c4 * 16u,
                  src + (size_t)row * N_DIM + c4 * 4);
        }
    };
    // paired-B staging: thread stages float4 chunk (pr = tid>>4, c = tid&15)
    auto stage_bp = [&](int n, int slot) {
        int pr = tid >> 4, c = tid & 15;
        cpa16(base + BP_OFF + (uint32_t)slot * BP_SLOT +
                  (uint32_t)pr * (BP_PITCH * 8) + (uint32_t)c * 16u,
              g_bp + (size_t)n * 256 + tid);
    };

    if (cnt > 0) {
        int staged_cib = -1, staged_slot = 3;
        auto px = [&](int j) -> int {     // stage x run for entry j if new
            int e = list_s[j];
            int cib = (e >> 12) & 127;
            if (cib != staged_cib) {
                staged_slot = (staged_slot + 1) & 3;
                stage_x(cib, staged_slot);
                staged_cib = cib;
            }
            return staged_slot;
        };

        // prologue: stage blocks 0,1 (one group)
        int q0 = px(0);
        stage_bp(list_s[0] & 0xFFF, 0);
        int q1 = q0;
        if (cnt > 1) { q1 = px(1); stage_bp(list_s[1] & 0xFFF, 1); }
        CP_COMMIT();

        uint32_t afr[4][4];
        int frag_cib = -1;
        const int S = (cnt + 1) >> 1;

        for (int s = 0; s < S; s++) {
            const int i0 = 2 * s, i1 = 2 * s + 1;

            CP_WAIT0();            // own copies from previous super-iter done
            __syncthreads();       // everyone waited -> all staged data visible

            // stage blocks i0+2, i1+2 (overlaps with compute below)
            int q2 = q1, q3 = q1;
            if (i0 + 2 < cnt) { q2 = px(i0 + 2); stage_bp(list_s[i0 + 2] & 0xFFF, (i0 + 2) & 3); }
            if (i1 + 2 < cnt) { q3 = px(i1 + 2); stage_bp(list_s[i1 + 2] & 0xFFF, (i1 + 2) & 3); }
            CP_COMMIT();

            // ---- compute block i0 ----
            {
                int vi  = list_s[i0];
                int lco = (vi >> 19) & 3;
                int cib = (vi >> 12) & 127;
                if (cib != frag_cib) {
                    load_afrags(afr, base + XS_OFF + (uint32_t)q0 * XS_SLOT +
                                     (uint32_t)(16 * w) * (XS_STRIDE * 4), kq, nq);
                    frag_cib = cib;
                }
                uint32_t bpb = base + BP_OFF + (uint32_t)(i0 & 3) * BP_SLOT;
                switch (lco) {
                    case 0: compute_block<0>(acc, afr, bpb, kq, nq); break;
                    case 1: compute_block<1>(acc, afr, bpb, kq, nq); break;
                    case 2: compute_block<2>(acc, afr, bpb, kq, nq); break;
                    default: compute_block<3>(acc, afr, bpb, kq, nq); break;
                }
            }
            // ---- compute block i1 ----
            if (i1 < cnt) {
                int vi  = list_s[i1];
                int lco = (vi >> 19) & 3;
                int cib = (vi >> 12) & 127;
                if (cib != frag_cib) {
                    load_afrags(afr, base + XS_OFF + (uint32_t)q1 * XS_SLOT +
                                     (uint32_t)(16 * w) * (XS_STRIDE * 4), kq, nq);
                    frag_cib = cib;
                }
                uint32_t bpb = base + BP_OFF + (uint32_t)(i1 & 3) * BP_SLOT;
                switch (lco) {
                    case 0: compute_block<0>(acc, afr, bpb, kq, nq); break;
                    case 1: compute_block<1>(acc, afr, bpb, kq, nq); break;
                    case 2: compute_block<2>(acc, afr, bpb, kq, nq); break;
                    default: compute_block<3>(acc, afr, bpb, kq, nq); break;
                }
            }

            q0 = q2; q1 = q3;
        }
    }

    // ---- epilogue: bias + relu ----
    {
        int r = 16 * w + nq;
        size_t rb0 = (size_t)(by * 128 + r) * N_DIM + g * GCOLS;
        size_t rb1 = rb0 + 8 * (size_t)N_DIM;
#pragma unroll
        for (int nt = 0; nt < 16; nt++) {
            int c = nt * 8 + 2 * kq;
            float b0 = bias_s[c], b1 = bias_s[c + 1];
            float2 v0, v1;
            v0.x = fmaxf(acc[nt][0] + b0, 0.f);
            v0.y = fmaxf(acc[nt][1] + b1, 0.f);
            v1.x = fmaxf(acc[nt][2] + b0, 0.f);
            v1.y = fmaxf(acc[nt][3] + b1, 0.f);
            *(float2*)(out + rb0 + c) = v0;
            *(float2*)(out + rb1 + c) = v1;
        }
    }
}

extern "C" void kernel_launch(void* const* d_in, const int* in_sizes, int n_in,
                              void* d_out, int out_size) {
    const float* x    = (const float*)d_in[0];
    const float* kern = (const float*)d_in[1];
    const float* bias = (const float*)d_in[2];
    const int*   ci   = (const int*)d_in[3];
    const int*   co   = (const int*)d_in[4];
    float* out = (float*)d_out;

    cudaFuncSetAttribute(bs_mma_kernel, cudaFuncAttributeMaxDynamicSharedMemorySize, SMEM_DYN);

    convert_b_kernel<<<NBLKS, 256>>>(kern);
    build_lists_kernel<<<GROUPS, NTHR>>>(ci, co);
    dim3 grid(GROUPS, BATCH / 128);
    bs_mma_kernel<<<grid, NTHR, SMEM_DYN>>>(x, bias, out);
}